// round 3
// baseline (speedup 1.0000x reference)
#include <cuda_runtime.h>

// Problem constants (fixed shapes)
#define V_N 50000
#define E_N 800000
#define TM  64     // edge/node rows per block tile
#define NT  256    // threads per block

// Scratch (static device arrays — no runtime allocation)
__device__ float g_m1[(size_t)E_N * 128];   // layer-1 activations (409.6 MB)
__device__ float g_agg[(size_t)V_N * 128];  // scatter-add accumulator (25.6 MB)

// ---------------------------------------------------------------------------
// Zero the aggregation buffer
// ---------------------------------------------------------------------------
__global__ void k_zero_agg() {
    const int n4 = V_N * 128 / 4;
    float4 z = make_float4(0.f, 0.f, 0.f, 0.f);
    for (int i = blockIdx.x * blockDim.x + threadIdx.x; i < n4;
         i += gridDim.x * blockDim.x)
        ((float4*)g_agg)[i] = z;
}

// ---------------------------------------------------------------------------
// Edge MLP layer 1: m1 = relu([h[src], h[dst]] @ W1 + b1)
// W1 (256x128 fp32 = 128KB) staged in smem once per persistent block.
// Block tile: 64 edges x 128 outputs, 8x4 micro-tile per thread.
// NOTE: edge_index is int32 (JAX x64 disabled downcasts int64 -> int32).
// ---------------------------------------------------------------------------
__global__ __launch_bounds__(NT, 1) void k_edge1(
    const float* __restrict__ h, const int* __restrict__ ei,
    const float* __restrict__ W1, const float* __restrict__ b1) {
    extern __shared__ float sm[];
    float* W1s = sm;                     // 256*128
    float* b1s = W1s + 256 * 128;        // 128
    float* Xs  = b1s + 128;              // 64*256
    int*   idx = (int*)(Xs + TM * 256);  // 2*64

    const int tid = threadIdx.x;
    for (int i = tid; i < 256 * 128 / 4; i += NT)
        ((float4*)W1s)[i] = ((const float4*)W1)[i];
    if (tid < 128) b1s[tid] = b1[tid];

    const int tx = tid & 31;   // output col group: cols tx*4..tx*4+3
    const int ty = tid >> 5;   // row group: rows ty*8..ty*8+7
    const float4* h4 = (const float4*)h;
    const int numTiles = E_N / TM;  // 12500 exact

    for (int tile = blockIdx.x; tile < numTiles; tile += gridDim.x) {
        const int e0 = tile * TM;
        __syncthreads();
        if (tid < TM) {
            idx[tid]      = ei[e0 + tid];        // src
            idx[TM + tid] = ei[E_N + e0 + tid];  // dst
        }
        __syncthreads();
        // Stage X tile: 64 rows x 256 cols ([h[src], h[dst]])
        for (int i = tid; i < TM * 64; i += NT) {
            int r = i >> 6, j = i & 63;
            int node = (j < 32) ? idx[r] : idx[TM + r];
            ((float4*)Xs)[i] = h4[(size_t)node * 32 + (j & 31)];
        }
        __syncthreads();

        float acc[8][4];
#pragma unroll
        for (int i = 0; i < 8; i++)
#pragma unroll
            for (int c = 0; c < 4; c++) acc[i][c] = 0.f;

        const float* xb = Xs + ty * 8 * 256;
#pragma unroll 4
        for (int k = 0; k < 256; k++) {
            float4 w = ((const float4*)(W1s + k * 128))[tx];
#pragma unroll
            for (int i = 0; i < 8; i++) {
                float x = xb[i * 256 + k];
                acc[i][0] = fmaf(x, w.x, acc[i][0]);
                acc[i][1] = fmaf(x, w.y, acc[i][1]);
                acc[i][2] = fmaf(x, w.z, acc[i][2]);
                acc[i][3] = fmaf(x, w.w, acc[i][3]);
            }
        }
        float4 bb = ((const float4*)b1s)[tx];
#pragma unroll
        for (int i = 0; i < 8; i++) {
            size_t e = (size_t)e0 + ty * 8 + i;
            float4 o;
            o.x = fmaxf(acc[i][0] + bb.x, 0.f);
            o.y = fmaxf(acc[i][1] + bb.y, 0.f);
            o.z = fmaxf(acc[i][2] + bb.z, 0.f);
            o.w = fmaxf(acc[i][3] + bb.w, 0.f);
            ((float4*)(g_m1 + e * 128))[tx] = o;
        }
    }
}

// ---------------------------------------------------------------------------
// Edge MLP layers 2+3 + scatter-add:
//   m2 = relu(m1 @ W2 + b2); msg = m2 @ W3 + b3; atomicAdd into g_agg[dst]
// ---------------------------------------------------------------------------
__global__ __launch_bounds__(NT, 1) void k_edge23(
    const int* __restrict__ ei,
    const float* __restrict__ W2, const float* __restrict__ b2,
    const float* __restrict__ W3, const float* __restrict__ b3) {
    extern __shared__ float sm[];
    float* W2s = sm;                       // 128*128
    float* W3s = W2s + 128 * 128;          // 128*128
    float* b2s = W3s + 128 * 128;          // 128
    float* b3s = b2s + 128;                // 128
    float* M1s = b3s + 128;                // 64*128
    float* M2s = M1s + TM * 128;           // 64*128
    int*   dsts = (int*)(M2s + TM * 128);  // 64

    const int tid = threadIdx.x;
    for (int i = tid; i < 128 * 128 / 4; i += NT) {
        ((float4*)W2s)[i] = ((const float4*)W2)[i];
        ((float4*)W3s)[i] = ((const float4*)W3)[i];
    }
    if (tid < 128) { b2s[tid] = b2[tid]; b3s[tid] = b3[tid]; }

    const int tx = tid & 31, ty = tid >> 5;
    const int numTiles = E_N / TM;

    for (int tile = blockIdx.x; tile < numTiles; tile += gridDim.x) {
        const int e0 = tile * TM;
        __syncthreads();
        if (tid < TM) dsts[tid] = ei[E_N + e0 + tid];
        const float4* src4 = (const float4*)(g_m1 + (size_t)e0 * 128);
        for (int i = tid; i < TM * 32; i += NT) ((float4*)M1s)[i] = src4[i];
        __syncthreads();

        // GEMM 1: M2 = relu(M1 @ W2 + b2)
        float acc[8][4];
#pragma unroll
        for (int i = 0; i < 8; i++)
#pragma unroll
            for (int c = 0; c < 4; c++) acc[i][c] = 0.f;
        {
            const float* xb = M1s + ty * 8 * 128;
#pragma unroll 4
            for (int k = 0; k < 128; k++) {
                float4 w = ((const float4*)(W2s + k * 128))[tx];
#pragma unroll
                for (int i = 0; i < 8; i++) {
                    float x = xb[i * 128 + k];
                    acc[i][0] = fmaf(x, w.x, acc[i][0]);
                    acc[i][1] = fmaf(x, w.y, acc[i][1]);
                    acc[i][2] = fmaf(x, w.z, acc[i][2]);
                    acc[i][3] = fmaf(x, w.w, acc[i][3]);
                }
            }
        }
        float4 b2v = ((const float4*)b2s)[tx];
#pragma unroll
        for (int i = 0; i < 8; i++) {
            float4 o;
            o.x = fmaxf(acc[i][0] + b2v.x, 0.f);
            o.y = fmaxf(acc[i][1] + b2v.y, 0.f);
            o.z = fmaxf(acc[i][2] + b2v.z, 0.f);
            o.w = fmaxf(acc[i][3] + b2v.w, 0.f);
            ((float4*)(M2s + (ty * 8 + i) * 128))[tx] = o;
        }
        __syncthreads();

        // GEMM 2: msg = M2 @ W3 + b3 ; scatter
#pragma unroll
        for (int i = 0; i < 8; i++)
#pragma unroll
            for (int c = 0; c < 4; c++) acc[i][c] = 0.f;
        {
            const float* xb = M2s + ty * 8 * 128;
#pragma unroll 4
            for (int k = 0; k < 128; k++) {
                float4 w = ((const float4*)(W3s + k * 128))[tx];
#pragma unroll
                for (int i = 0; i < 8; i++) {
                    float x = xb[i * 128 + k];
                    acc[i][0] = fmaf(x, w.x, acc[i][0]);
                    acc[i][1] = fmaf(x, w.y, acc[i][1]);
                    acc[i][2] = fmaf(x, w.z, acc[i][2]);
                    acc[i][3] = fmaf(x, w.w, acc[i][3]);
                }
            }
        }
        float4 b3v = ((const float4*)b3s)[tx];
#pragma unroll
        for (int i = 0; i < 8; i++) {
            int d = dsts[ty * 8 + i];
            float* ap = g_agg + (size_t)d * 128 + tx * 4;
            atomicAdd(ap + 0, acc[i][0] + b3v.x);
            atomicAdd(ap + 1, acc[i][1] + b3v.y);
            atomicAdd(ap + 2, acc[i][2] + b3v.z);
            atomicAdd(ap + 3, acc[i][3] + b3v.w);
        }
    }
}

// ---------------------------------------------------------------------------
// Node MLP: out = relu([h, agg] @ Wn1 + bn1) @ Wn2 + bn2
// Wn1 (128KB) + Wn2 (64KB) + one 64x128 staging tile fit in 230.4KB smem.
// ---------------------------------------------------------------------------
__global__ __launch_bounds__(NT, 1) void k_node(
    const float* __restrict__ h,
    const float* __restrict__ Wn1, const float* __restrict__ bn1,
    const float* __restrict__ Wn2, const float* __restrict__ bn2,
    float* __restrict__ out) {
    extern __shared__ float sm[];
    float* Wn1s = sm;                 // 256*128
    float* Wn2s = Wn1s + 256 * 128;   // 128*128
    float* bn1s = Wn2s + 128 * 128;   // 128
    float* bn2s = bn1s + 128;         // 128
    float* Xs   = bn2s + 128;         // 64*128 (reused as T after relu)

    const int tid = threadIdx.x;
    for (int i = tid; i < 256 * 128 / 4; i += NT)
        ((float4*)Wn1s)[i] = ((const float4*)Wn1)[i];
    for (int i = tid; i < 128 * 128 / 4; i += NT)
        ((float4*)Wn2s)[i] = ((const float4*)Wn2)[i];
    if (tid < 128) { bn1s[tid] = bn1[tid]; bn2s[tid] = bn2[tid]; }

    const int tx = tid & 31, ty = tid >> 5;
    const float4* h4 = (const float4*)h;
    const float4* a4 = (const float4*)g_agg;
    const int numTiles = (V_N + TM - 1) / TM;
    const float4 z = make_float4(0.f, 0.f, 0.f, 0.f);

    for (int tile = blockIdx.x; tile < numTiles; tile += gridDim.x) {
        const int n0 = tile * TM;
        float acc[8][4];
#pragma unroll
        for (int i = 0; i < 8; i++)
#pragma unroll
            for (int c = 0; c < 4; c++) acc[i][c] = 0.f;

        // K-chunk 1: h
        __syncthreads();
        for (int i = tid; i < TM * 32; i += NT) {
            int r = i >> 5, j = i & 31;
            int node = n0 + r;
            ((float4*)Xs)[i] = (node < V_N) ? h4[(size_t)node * 32 + j] : z;
        }
        __syncthreads();
        {
            const float* xb = Xs + ty * 8 * 128;
#pragma unroll 4
            for (int k = 0; k < 128; k++) {
                float4 w = ((const float4*)(Wn1s + k * 128))[tx];
#pragma unroll
                for (int i = 0; i < 8; i++) {
                    float x = xb[i * 128 + k];
                    acc[i][0] = fmaf(x, w.x, acc[i][0]);
                    acc[i][1] = fmaf(x, w.y, acc[i][1]);
                    acc[i][2] = fmaf(x, w.z, acc[i][2]);
                    acc[i][3] = fmaf(x, w.w, acc[i][3]);
                }
            }
        }
        // K-chunk 2: agg
        __syncthreads();
        for (int i = tid; i < TM * 32; i += NT) {
            int r = i >> 5, j = i & 31;
            int node = n0 + r;
            ((float4*)Xs)[i] = (node < V_N) ? a4[(size_t)node * 32 + j] : z;
        }
        __syncthreads();
        {
            const float* xb = Xs + ty * 8 * 128;
#pragma unroll 4
            for (int k = 0; k < 128; k++) {
                float4 w = ((const float4*)(Wn1s + (128 + k) * 128))[tx];
#pragma unroll
                for (int i = 0; i < 8; i++) {
                    float x = xb[i * 128 + k];
                    acc[i][0] = fmaf(x, w.x, acc[i][0]);
                    acc[i][1] = fmaf(x, w.y, acc[i][1]);
                    acc[i][2] = fmaf(x, w.z, acc[i][2]);
                    acc[i][3] = fmaf(x, w.w, acc[i][3]);
                }
            }
        }
        // relu + bn1 -> T (reuse Xs)
        __syncthreads();
        float4 b1v = ((const float4*)bn1s)[tx];
#pragma unroll
        for (int i = 0; i < 8; i++) {
            float4 o;
            o.x = fmaxf(acc[i][0] + b1v.x, 0.f);
            o.y = fmaxf(acc[i][1] + b1v.y, 0.f);
            o.z = fmaxf(acc[i][2] + b1v.z, 0.f);
            o.w = fmaxf(acc[i][3] + b1v.w, 0.f);
            ((float4*)(Xs + (ty * 8 + i) * 128))[tx] = o;
        }
        __syncthreads();
        // GEMM 2: out = T @ Wn2 + bn2
#pragma unroll
        for (int i = 0; i < 8; i++)
#pragma unroll
            for (int c = 0; c < 4; c++) acc[i][c] = 0.f;
        {
            const float* xb = Xs + ty * 8 * 128;
#pragma unroll 4
            for (int k = 0; k < 128; k++) {
                float4 w = ((const float4*)(Wn2s + k * 128))[tx];
#pragma unroll
                for (int i = 0; i < 8; i++) {
                    float x = xb[i * 128 + k];
                    acc[i][0] = fmaf(x, w.x, acc[i][0]);
                    acc[i][1] = fmaf(x, w.y, acc[i][1]);
                    acc[i][2] = fmaf(x, w.z, acc[i][2]);
                    acc[i][3] = fmaf(x, w.w, acc[i][3]);
                }
            }
        }
        float4 b2v = ((const float4*)bn2s)[tx];
#pragma unroll
        for (int i = 0; i < 8; i++) {
            int node = n0 + ty * 8 + i;
            if (node < V_N) {
                float4 o;
                o.x = acc[i][0] + b2v.x;
                o.y = acc[i][1] + b2v.y;
                o.z = acc[i][2] + b2v.z;
                o.w = acc[i][3] + b2v.w;
                ((float4*)(out + (size_t)node * 128))[tx] = o;
            }
        }
    }
}

// ---------------------------------------------------------------------------
extern "C" void kernel_launch(void* const* d_in, const int* in_sizes, int n_in,
                              void* d_out, int out_size) {
    const float* h   = (const float*)d_in[0];
    const int*   ei  = (const int*)d_in[1];   // int32 (JAX x64 disabled)
    const float* W1  = (const float*)d_in[2];
    const float* b1  = (const float*)d_in[3];
    const float* W2  = (const float*)d_in[4];
    const float* b2  = (const float*)d_in[5];
    const float* W3  = (const float*)d_in[6];
    const float* b3  = (const float*)d_in[7];
    const float* Wn1 = (const float*)d_in[8];
    const float* bn1 = (const float*)d_in[9];
    const float* Wn2 = (const float*)d_in[10];
    const float* bn2 = (const float*)d_in[11];
    float*       out = (float*)d_out;

    const int smem1 = (256 * 128 + 128 + TM * 256) * 4 + TM * 2 * 4;       // ~197.6 KB
    const int smem2 = (128 * 128 * 2 + 256 + TM * 128 * 2) * 4 + TM * 4;   // ~197.9 KB
    const int smem3 = (256 * 128 + 128 * 128 + 256 + TM * 128) * 4;        // 230.4 KB

    cudaFuncSetAttribute(k_edge1,  cudaFuncAttributeMaxDynamicSharedMemorySize, smem1);
    cudaFuncSetAttribute(k_edge23, cudaFuncAttributeMaxDynamicSharedMemorySize, smem2);
    cudaFuncSetAttribute(k_node,   cudaFuncAttributeMaxDynamicSharedMemorySize, smem3);

    k_zero_agg<<<1024, 256>>>();
    k_edge1<<<152, NT, smem1>>>(h, ei, W1, b1);
    k_edge23<<<152, NT, smem2>>>(ei, W2, b2, W3, b3);
    k_node<<<152, NT, smem3>>>(h, Wn1, bn1, Wn2, bn2, out);
}

// round 5
// speedup vs baseline: 3.1452x; 3.1452x over previous
#include <cuda_runtime.h>
#include <cuda_bf16.h>
#include <cstdint>

// Problem constants (fixed shapes)
#define V_N 50000
#define E_N 800000
#define TM  64     // node-kernel rows per tile
#define NT  256

// Scratch (static device arrays — no runtime allocation)
__device__ float g_agg[(size_t)V_N * 128];  // scatter-add accumulator (25.6 MB)

// ============================================================================
// Warp-level MMA helpers (base PTX: ldmatrix sm_75+, mma.sync bf16 sm_80+)
// ============================================================================
__device__ __forceinline__ uint32_t smem_u32(const void* p) {
    uint32_t a;
    asm("{ .reg .u64 t; cvta.to.shared.u64 t, %1; cvt.u32.u64 %0, t; }"
        : "=r"(a) : "l"(p));
    return a;
}

__device__ __forceinline__ void ldsm_x4(uint32_t* r, uint32_t addr) {
    asm volatile("ldmatrix.sync.aligned.m8n8.x4.shared.b16 {%0,%1,%2,%3}, [%4];"
                 : "=r"(r[0]), "=r"(r[1]), "=r"(r[2]), "=r"(r[3]) : "r"(addr));
}
__device__ __forceinline__ void ldsm_x4_t(uint32_t* r, uint32_t addr) {
    asm volatile("ldmatrix.sync.aligned.m8n8.x4.trans.shared.b16 {%0,%1,%2,%3}, [%4];"
                 : "=r"(r[0]), "=r"(r[1]), "=r"(r[2]), "=r"(r[3]) : "r"(addr));
}
__device__ __forceinline__ void mma_bf16(float* d, const uint32_t* a, const uint32_t* b) {
    asm volatile(
        "mma.sync.aligned.m16n8k16.row.col.f32.bf16.bf16.f32 "
        "{%0,%1,%2,%3}, {%4,%5,%6,%7}, {%8,%9}, {%0,%1,%2,%3};"
        : "+f"(d[0]), "+f"(d[1]), "+f"(d[2]), "+f"(d[3])
        : "r"(a[0]), "r"(a[1]), "r"(a[2]), "r"(a[3]), "r"(b[0]), "r"(b[1]));
}
__device__ __forceinline__ uint32_t pack2(float a, float b) {
    __nv_bfloat162 p = __floats2bfloat162_rn(a, b);
    return *(uint32_t*)&p;
}
__device__ __forceinline__ void red_add_v4(float* p, float a, float b, float c, float d) {
    asm volatile("red.global.add.v4.f32 [%0], {%1, %2, %3, %4};"
                 :: "l"(p), "f"(a), "f"(b), "f"(c), "f"(d) : "memory");
}

// ---------------------------------------------------------------------------
// SMEM layout for the edge kernel (bytes). Weight rows padded to 272B,
// activation rows to 528B -> conflict-free ldmatrix (68/132 words mod 32 = 4).
// ---------------------------------------------------------------------------
#define SM_IDX 0        // 128 ints (src[64], dst[64])
#define SM_BB1 512      // 128 floats
#define SM_BB2 1024
#define SM_BB3 1536
#define SM_W1  2048     // 256 rows x 272B = 69632
#define SM_W2  71680    // 128 x 272B = 34816
#define SM_W3  106496   // 128 x 272B = 34816
#define SM_A2  141312   // 64 x 272B  = 17408 (bf16 activations L2 input)
#define SM_XS  158720   // 64 x 528B  = 33792 (X input / A3 / fp32 staging)
#define SM_EDGE_TOTAL 192512

#define WPITCH 272
#define XPITCH 528

// Warp-tile GEMM: D(32x32) += A(32xK) @ W(KxN)^(col frag), A rows at
// wr*32, W cols at wc*32. A base pitch AP, weights pitch 272.
template <int NK, int AP>
__device__ __forceinline__ void gemm_tile(uint32_t abase, uint32_t wbase,
                                          int wr, int wc, int lane,
                                          float d[2][4][4]) {
    const int l15 = lane & 15;
    const int kh  = (lane >> 4) << 3;   // 0 or 8
#pragma unroll
    for (int mi = 0; mi < 2; mi++)
#pragma unroll
        for (int ni = 0; ni < 4; ni++)
#pragma unroll
            for (int x = 0; x < 4; x++) d[mi][ni][x] = 0.f;

#pragma unroll
    for (int ks = 0; ks < NK; ks++) {
        uint32_t a[2][4], b[4][2];
#pragma unroll
        for (int mi = 0; mi < 2; mi++) {
            uint32_t addr = abase + (uint32_t)((wr * 32 + mi * 16 + l15) * AP +
                                               (ks * 16 + kh) * 2);
            ldsm_x4(a[mi], addr);
        }
#pragma unroll
        for (int nj = 0; nj < 2; nj++) {
            uint32_t addr = wbase + (uint32_t)((ks * 16 + l15) * WPITCH +
                                               (wc * 32 + nj * 16 + kh) * 2);
            uint32_t t[4];
            ldsm_x4_t(t, addr);
            b[2 * nj][0] = t[0]; b[2 * nj][1] = t[1];
            b[2 * nj + 1][0] = t[2]; b[2 * nj + 1][1] = t[3];
        }
#pragma unroll
        for (int mi = 0; mi < 2; mi++)
#pragma unroll
            for (int ni = 0; ni < 4; ni++)
                mma_bf16(d[mi][ni], a[mi], b[ni]);
    }
}

// Epilogue: relu(d + bias) -> bf16 tile at dstbase (pitch P bytes)
template <int P>
__device__ __forceinline__ void epi_relu_bf16(char* dstbase, const float* bias,
                                              float d[2][4][4],
                                              int wr, int wc, int lane) {
    const int g = lane >> 2, q = lane & 3;
#pragma unroll
    for (int mi = 0; mi < 2; mi++) {
        const int rA = wr * 32 + mi * 16 + g;
#pragma unroll
        for (int ni = 0; ni < 4; ni++) {
            const int c = wc * 32 + ni * 8 + 2 * q;
            float2 bb = *(const float2*)&bias[c];
            float v0 = fmaxf(d[mi][ni][0] + bb.x, 0.f);
            float v1 = fmaxf(d[mi][ni][1] + bb.y, 0.f);
            float v2 = fmaxf(d[mi][ni][2] + bb.x, 0.f);
            float v3 = fmaxf(d[mi][ni][3] + bb.y, 0.f);
            *(uint32_t*)(dstbase + rA * P + c * 2)       = pack2(v0, v1);
            *(uint32_t*)(dstbase + (rA + 8) * P + c * 2) = pack2(v2, v3);
        }
    }
}

// ---------------------------------------------------------------------------
// Zero the aggregation buffer
// ---------------------------------------------------------------------------
__global__ void k_zero_agg() {
    const int n4 = V_N * 128 / 4;
    float4 z = make_float4(0.f, 0.f, 0.f, 0.f);
    for (int i = blockIdx.x * blockDim.x + threadIdx.x; i < n4;
         i += gridDim.x * blockDim.x)
        ((float4*)g_agg)[i] = z;
}

// ---------------------------------------------------------------------------
// Fused edge MLP (3 layers, bf16 mma.sync) + vectorized scatter-add.
// Tile = 64 edges x 128 outputs. 8 warps: grid 2(rows of 32) x 4(cols of 32).
// ---------------------------------------------------------------------------
__global__ __launch_bounds__(NT, 1) void k_edge(
    const float* __restrict__ h, const int* __restrict__ ei,
    const float* __restrict__ W1, const float* __restrict__ b1,
    const float* __restrict__ W2, const float* __restrict__ b2,
    const float* __restrict__ W3, const float* __restrict__ b3)
{
    extern __shared__ __align__(16) char sm[];
    int*   idxs = (int*)(sm + SM_IDX);
    float* b1s  = (float*)(sm + SM_BB1);
    float* b2s  = (float*)(sm + SM_BB2);
    float* b3s  = (float*)(sm + SM_BB3);
    const uint32_t sbase = smem_u32(sm);
    const uint32_t sW1 = sbase + SM_W1, sW2 = sbase + SM_W2, sW3 = sbase + SM_W3;
    const uint32_t sA2 = sbase + SM_A2, sXS = sbase + SM_XS;

    const int tid = threadIdx.x, wid = tid >> 5, lane = tid & 31;
    const int wr = wid & 1, wc = wid >> 1;

    // Stage weights as bf16 (row-major [k][n], padded pitch) + biases
    for (int i = tid; i < 256 * 128; i += NT) {
        int k = i >> 7, n = i & 127;
        *(__nv_bfloat16*)(sm + SM_W1 + k * WPITCH + n * 2) = __float2bfloat16(W1[i]);
    }
    for (int i = tid; i < 128 * 128; i += NT) {
        int k = i >> 7, n = i & 127;
        *(__nv_bfloat16*)(sm + SM_W2 + k * WPITCH + n * 2) = __float2bfloat16(W2[i]);
        *(__nv_bfloat16*)(sm + SM_W3 + k * WPITCH + n * 2) = __float2bfloat16(W3[i]);
    }
    if (tid < 128) { b1s[tid] = b1[tid]; b2s[tid] = b2[tid]; b3s[tid] = b3[tid]; }
    __syncthreads();

    const float4* h4 = (const float4*)h;
    float d[2][4][4];
    const int numTiles = E_N / 64;   // 12500

    for (int tile = blockIdx.x; tile < numTiles; tile += gridDim.x) {
        const int e0 = tile * 64;

        // ---- indices + gather [h[src] | h[dst]] -> Xs bf16 (64 x 256) ----
        if (tid < 64)       idxs[tid] = ei[e0 + tid];
        else if (tid < 128) idxs[tid] = ei[E_N + e0 + (tid - 64)];
        __syncthreads();
        for (int i = tid; i < 64 * 64; i += NT) {
            int r = i >> 6, j = i & 63;
            int node = (j < 32) ? idxs[r] : idxs[64 + r];
            float4 v = h4[(size_t)node * 32 + (j & 31)];
            uint2 u;
            u.x = pack2(v.x, v.y);
            u.y = pack2(v.z, v.w);
            *(uint2*)(sm + SM_XS + r * XPITCH + j * 8) = u;
        }
        __syncthreads();

        // ---- GEMM1 (K=256): A2 = relu(X @ W1 + b1) ----
        gemm_tile<16, XPITCH>(sXS, sW1, wr, wc, lane, d);
        epi_relu_bf16<WPITCH>(sm + SM_A2, b1s, d, wr, wc, lane);
        __syncthreads();

        // ---- GEMM2 (K=128): A3 = relu(A2 @ W2 + b2) -> reuse Xs ----
        gemm_tile<8, WPITCH>(sA2, sW2, wr, wc, lane, d);
        epi_relu_bf16<XPITCH>(sm + SM_XS, b2s, d, wr, wc, lane);
        __syncthreads();

        // ---- GEMM3 (K=128): D3 = A3 @ W3 (bias added during scatter) ----
        gemm_tile<8, XPITCH>(sXS, sW3, wr, wc, lane, d);
        __syncthreads();   // all warps done reading A3 before staging overwrites

        // fp32 staging into Xs (pitch 528B = 132 floats)
        {
            const int g = lane >> 2, q = lane & 3;
#pragma unroll
            for (int mi = 0; mi < 2; mi++) {
                const int rA = wr * 32 + mi * 16 + g;
#pragma unroll
                for (int ni = 0; ni < 4; ni++) {
                    const int c = wc * 32 + ni * 8 + 2 * q;
                    *(float2*)(sm + SM_XS + rA * XPITCH + c * 4) =
                        make_float2(d[mi][ni][0], d[mi][ni][1]);
                    *(float2*)(sm + SM_XS + (rA + 8) * XPITCH + c * 4) =
                        make_float2(d[mi][ni][2], d[mi][ni][3]);
                }
            }
        }
        __syncthreads();

        // ---- vectorized scatter-add: g_agg[dst] += D3 + b3 ----
        {
            const int row = tid >> 2, cg = (tid & 3) * 32;
            const int dst = idxs[64 + row];
            float* base = g_agg + (size_t)dst * 128 + cg;
            const float* srow = (const float*)(sm + SM_XS + row * XPITCH) + cg;
#pragma unroll
            for (int j = 0; j < 8; j++) {
                float4 v  = *(const float4*)(srow + 4 * j);
                float4 bb = *(const float4*)&b3s[cg + 4 * j];
                red_add_v4(base + 4 * j, v.x + bb.x, v.y + bb.y,
                           v.z + bb.z, v.w + bb.w);
            }
        }
        __syncthreads();   // protect idxs/Xs before next tile
    }
}

// ---------------------------------------------------------------------------
// Node MLP (fp32 FFMA): out = relu([h, agg] @ Wn1 + bn1) @ Wn2 + bn2
// ---------------------------------------------------------------------------
__global__ __launch_bounds__(NT, 1) void k_node(
    const float* __restrict__ h,
    const float* __restrict__ Wn1, const float* __restrict__ bn1,
    const float* __restrict__ Wn2, const float* __restrict__ bn2,
    float* __restrict__ out) {
    extern __shared__ float smf[];
    float* Wn1s = smf;                 // 256*128
    float* Wn2s = Wn1s + 256 * 128;    // 128*128
    float* bn1s = Wn2s + 128 * 128;    // 128
    float* bn2s = bn1s + 128;          // 128
    float* Xs   = bn2s + 128;          // 64*128

    const int tid = threadIdx.x;
    for (int i = tid; i < 256 * 128 / 4; i += NT)
        ((float4*)Wn1s)[i] = ((const float4*)Wn1)[i];
    for (int i = tid; i < 128 * 128 / 4; i += NT)
        ((float4*)Wn2s)[i] = ((const float4*)Wn2)[i];
    if (tid < 128) { bn1s[tid] = bn1[tid]; bn2s[tid] = bn2[tid]; }

    const int tx = tid & 31, ty = tid >> 5;
    const float4* h4 = (const float4*)h;
    const float4* a4 = (const float4*)g_agg;
    const int numTiles = (V_N + TM - 1) / TM;
    const float4 z = make_float4(0.f, 0.f, 0.f, 0.f);

    for (int tile = blockIdx.x; tile < numTiles; tile += gridDim.x) {
        const int n0 = tile * TM;
        float acc[8][4];
#pragma unroll
        for (int i = 0; i < 8; i++)
#pragma unroll
            for (int c = 0; c < 4; c++) acc[i][c] = 0.f;

        __syncthreads();
        for (int i = tid; i < TM * 32; i += NT) {
            int rr = i >> 5, j = i & 31;
            int node = n0 + rr;
            ((float4*)Xs)[i] = (node < V_N) ? h4[(size_t)node * 32 + j] : z;
        }
        __syncthreads();
        {
            const float* xb = Xs + ty * 8 * 128;
#pragma unroll 4
            for (int k = 0; k < 128; k++) {
                float4 w = ((const float4*)(Wn1s + k * 128))[tx];
#pragma unroll
                for (int i = 0; i < 8; i++) {
                    float x = xb[i * 128 + k];
                    acc[i][0] = fmaf(x, w.x, acc[i][0]);
                    acc[i][1] = fmaf(x, w.y, acc[i][1]);
                    acc[i][2] = fmaf(x, w.z, acc[i][2]);
                    acc[i][3] = fmaf(x, w.w, acc[i][3]);
                }
            }
        }
        __syncthreads();
        for (int i = tid; i < TM * 32; i += NT) {
            int rr = i >> 5, j = i & 31;
            int node = n0 + rr;
            ((float4*)Xs)[i] = (node < V_N) ? a4[(size_t)node * 32 + j] : z;
        }
        __syncthreads();
        {
            const float* xb = Xs + ty * 8 * 128;
#pragma unroll 4
            for (int k = 0; k < 128; k++) {
                float4 w = ((const float4*)(Wn1s + (128 + k) * 128))[tx];
#pragma unroll
                for (int i = 0; i < 8; i++) {
                    float x = xb[i * 128 + k];
                    acc[i][0] = fmaf(x, w.x, acc[i][0]);
                    acc[i][1] = fmaf(x, w.y, acc[i][1]);
                    acc[i][2] = fmaf(x, w.z, acc[i][2]);
                    acc[i][3] = fmaf(x, w.w, acc[i][3]);
                }
            }
        }
        __syncthreads();
        float4 b1v = ((const float4*)bn1s)[tx];
#pragma unroll
        for (int i = 0; i < 8; i++) {
            float4 o;
            o.x = fmaxf(acc[i][0] + b1v.x, 0.f);
            o.y = fmaxf(acc[i][1] + b1v.y, 0.f);
            o.z = fmaxf(acc[i][2] + b1v.z, 0.f);
            o.w = fmaxf(acc[i][3] + b1v.w, 0.f);
            ((float4*)(Xs + (ty * 8 + i) * 128))[tx] = o;
        }
        __syncthreads();
#pragma unroll
        for (int i = 0; i < 8; i++)
#pragma unroll
            for (int c = 0; c < 4; c++) acc[i][c] = 0.f;
        {
            const float* xb = Xs + ty * 8 * 128;
#pragma unroll 4
            for (int k = 0; k < 128; k++) {
                float4 w = ((const float4*)(Wn2s + k * 128))[tx];
#pragma unroll
                for (int i = 0; i < 8; i++) {
                    float x = xb[i * 128 + k];
                    acc[i][0] = fmaf(x, w.x, acc[i][0]);
                    acc[i][1] = fmaf(x, w.y, acc[i][1]);
                    acc[i][2] = fmaf(x, w.z, acc[i][2]);
                    acc[i][3] = fmaf(x, w.w, acc[i][3]);
                }
            }
        }
        float4 b2v = ((const float4*)bn2s)[tx];
#pragma unroll
        for (int i = 0; i < 8; i++) {
            int node = n0 + ty * 8 + i;
            if (node < V_N) {
                float4 o;
                o.x = acc[i][0] + b2v.x;
                o.y = acc[i][1] + b2v.y;
                o.z = acc[i][2] + b2v.z;
                o.w = acc[i][3] + b2v.w;
                ((float4*)(out + (size_t)node * 128))[tx] = o;
            }
        }
    }
}

// ---------------------------------------------------------------------------
extern "C" void kernel_launch(void* const* d_in, const int* in_sizes, int n_in,
                              void* d_out, int out_size) {
    const float* h   = (const float*)d_in[0];
    const int*   ei  = (const int*)d_in[1];   // int32 (JAX x64 disabled)
    const float* W1  = (const float*)d_in[2];
    const float* b1  = (const float*)d_in[3];
    const float* W2  = (const float*)d_in[4];
    const float* b2  = (const float*)d_in[5];
    const float* W3  = (const float*)d_in[6];
    const float* b3  = (const float*)d_in[7];
    const float* Wn1 = (const float*)d_in[8];
    const float* bn1 = (const float*)d_in[9];
    const float* Wn2 = (const float*)d_in[10];
    const float* bn2 = (const float*)d_in[11];
    float*       out = (float*)d_out;

    const int smemE = SM_EDGE_TOTAL;                                 // 192512
    const int smemN = (256 * 128 + 128 * 128 + 256 + TM * 128) * 4;  // 230400

    cudaFuncSetAttribute(k_edge, cudaFuncAttributeMaxDynamicSharedMemorySize, smemE);
    cudaFuncSetAttribute(k_node, cudaFuncAttributeMaxDynamicSharedMemorySize, smemN);

    k_zero_agg<<<512, 256>>>();
    k_edge<<<148, NT, smemE>>>(h, ei, W1, b1, W2, b2, W3, b3);
    k_node<<<152, NT, smemN>>>(h, Wn1, bn1, Wn2, bn2, out);
}